// round 12
// baseline (speedup 1.0000x reference)
#include <cuda_runtime.h>
#include <cstdint>

#define NN 100000
#define NE 1000000
#define D  64
#define MP 3

#define TILE 2048
#define TSH  11
#define NT ((NN + TILE - 1) / TILE)

// Scratch (__device__ globals per allocation-free rule)
__device__ float mg_h[(size_t)MP * NN * D];       // transformed features
__device__ float mg_deg[MP * NN];                 // dinv
__device__ unsigned long long mg_pack[MP * NN];   // count<<44 | fixp deg sum
__device__ int   mg_count[MP * NN];               // edges per dest node
__device__ int   mg_off[MP * NN];                 // tile-LOCAL exclusive offsets
__device__ int   mg_rank[(size_t)MP * NE];        // per-edge arrival rank
__device__ int2  mg_edge[(size_t)MP * NE];        // packed (src row, norm)
__device__ int   mg_tiletot[MP * NT];
__device__ int   mg_tileoff[MP * NT];
__device__ int   mg_sh;                           // 0 = int32 idx, 1 = int64

// ---------------------------------------------------------------------------
// Fused: zero pack; block 0 warp 0 sniffs edge dtype.
// ---------------------------------------------------------------------------
__global__ void mz_init(const int* __restrict__ ei32) {
    int i = blockIdx.x * blockDim.x + threadIdx.x;
    if (i < MP * NN) mg_pack[i] = 0ull;
    if (blockIdx.x == 0 && threadIdx.x < 32) {
        int t = threadIdx.x;
        int nz = 0;
        for (int k = 0; k < 8; k++) {
            int s = (t * 8 + k) * 1009;
            nz |= (ei32[2 * s + 1] != 0);
        }
        unsigned b = __ballot_sync(0xffffffffu, nz);
        if (t == 0) mg_sh = (b == 0u) ? 1 : 0;
    }
}

__device__ __forceinline__ int ld_idx(const int* p, size_t pos, int sh) {
    return p[pos << sh];
}

// ---------------------------------------------------------------------------
// One packed u64 atomic per edge: count++ AND deg += ew (2^-24 fixpoint).
// The returned old value's count field is this edge's rank at its dest node.
// ---------------------------------------------------------------------------
__global__ void mz_hist(const int* __restrict__ ei32,
                        const float* __restrict__ ew) {
    int mp = blockIdx.y;
    int sh = mg_sh;
    size_t colbase = (size_t)mp * 2 * NE + NE;
    const float* ewp = ew + (size_t)mp * NE;
    unsigned long long* pk = mg_pack + (size_t)mp * NN;
    int* rk = mg_rank + (size_t)mp * NE;
    int stride = gridDim.x * blockDim.x;
    for (int e = blockIdx.x * blockDim.x + threadIdx.x; e < NE; e += stride) {
        int c = ld_idx(ei32, colbase + e, sh);
        unsigned long long frac =
            (unsigned long long)__float2uint_rn(ewp[e] * 16777216.0f);
        unsigned long long old = atomicAdd(pk + c, (1ull << 44) | frac);
        rk[e] = (int)(old >> 44);
    }
}

// ---------------------------------------------------------------------------
// Phase A of decoupled scan: pack -> (count, dinv), tile-local off, tile totals.
// ---------------------------------------------------------------------------
__global__ __launch_bounds__(256) void mz_scanA() {
    __shared__ int wtot[8];
    __shared__ int wpre[8];
    int mp = blockIdx.y;
    int tile = blockIdx.x;
    int t = threadIdx.x;
    int lane = t & 31;
    int warp = t >> 5;
    const unsigned long long* pk = mg_pack + (size_t)mp * NN;
    int* cnt = mg_count + (size_t)mp * NN;
    int* off = mg_off + (size_t)mp * NN;
    float* deg = mg_deg + (size_t)mp * NN;

    int base = tile * TILE + t * 8;
    int v[8];
#pragma unroll
    for (int k = 0; k < 8; k++) {
        int i = base + k;
        if (i < NN) {
            unsigned long long p = pk[i];
            int c = (int)(p >> 44);
            float d = (float)(p & ((1ull << 44) - 1)) * (1.0f / 16777216.0f);
            v[k] = c;
            cnt[i] = c;
            deg[i] = (d > 0.f) ? rsqrtf(d) : 0.f;
        } else {
            v[k] = 0;
        }
    }
    int mysum = 0;
#pragma unroll
    for (int k = 0; k < 8; k++) mysum += v[k];

    int inc = mysum;
#pragma unroll
    for (int o = 1; o < 32; o <<= 1) {
        int n = __shfl_up_sync(0xffffffffu, inc, o);
        if (lane >= o) inc += n;
    }
    if (lane == 31) wtot[warp] = inc;
    __syncthreads();
    if (t == 0) {
        int run = 0;
#pragma unroll
        for (int w = 0; w < 8; w++) { wpre[w] = run; run += wtot[w]; }
        mg_tiletot[mp * NT + tile] = run;
    }
    __syncthreads();

    int excl = wpre[warp] + inc - mysum;
#pragma unroll
    for (int k = 0; k < 8; k++) {
        int i = base + k;
        if (i < NN) off[i] = excl;     // tile-LOCAL exclusive prefix
        excl += v[k];
    }
}

// Tiny: exclusive scan of NT tile totals per metapath.
__global__ __launch_bounds__(64) void mz_scanB() {
    __shared__ int s[64];
    int mp = blockIdx.x;
    int t = threadIdx.x;
    s[t] = (t < NT) ? mg_tiletot[mp * NT + t] : 0;
    __syncthreads();
    for (int d2 = 1; d2 < 64; d2 <<= 1) {
        int add = (t >= d2) ? s[t - d2] : 0;
        __syncthreads();
        s[t] += add;
        __syncthreads();
    }
    if (t < NT) mg_tileoff[mp * NT + t] = s[t] - mg_tiletot[mp * NT + t];
}

// ---------------------------------------------------------------------------
// GEMM via mma.sync.m16n8k8 tf32 (measured-good R9/R11 configuration).
// ---------------------------------------------------------------------------
#define XPAD 68
#define WPAD 72
#define SX_FLOATS (128 * XPAD)
#define SW_FLOATS (MP * 64 * WPAD)
#define GEMM_SMEM ((SX_FLOATS + SW_FLOATS) * 4)

__device__ __forceinline__ uint32_t f2tf32(float f) {
    uint32_t u;
    asm("cvt.rna.tf32.f32 %0, %1;" : "=r"(u) : "f"(f));
    return u;
}

__global__ __launch_bounds__(256) void mz_gemm_mma(const float* __restrict__ x,
                                                   const float* __restrict__ W) {
    extern __shared__ float smem[];
    float* sx = smem;                 // [128][XPAD]
    float* sW = smem + SX_FLOATS;     // [MP][64][WPAD]
    int t = threadIdx.x;
    int wid = t >> 5;
    int lane = t & 31;
    int rowbase = blockIdx.x * 128;

    const float4* x4 = (const float4*)x;
    for (int i = t; i < 2048; i += 256) {
        int row = i >> 4;
        int q = i & 15;
        float4 v = make_float4(0.f, 0.f, 0.f, 0.f);
        int grow = rowbase + row;
        if (grow < NN) v = x4[(size_t)grow * 16 + q];
        uint4 u = make_uint4(f2tf32(v.x), f2tf32(v.y), f2tf32(v.z), f2tf32(v.w));
        *(uint4*)(sx + row * XPAD + q * 4) = u;
    }
    const float4* W4 = (const float4*)W;
    for (int i = t; i < MP * 64 * 16; i += 256) {
        int mp = i >> 10;
        int rem = i & 1023;
        int k = rem >> 4;
        int q = rem & 15;
        float4 v = W4[i];
        uint4 u = make_uint4(f2tf32(v.x), f2tf32(v.y), f2tf32(v.z), f2tf32(v.w));
        *(uint4*)(sW + mp * 64 * WPAD + k * WPAD + q * 4) = u;
    }
    __syncthreads();

    int r = lane >> 2;
    int c = lane & 3;
    const uint32_t* sxu = (const uint32_t*)sx;
    const uint32_t* sWu = (const uint32_t*)sW;

    uint32_t a[8][4];
    int ar0 = (wid * 16 + r) * XPAD;
    int ar1 = (wid * 16 + r + 8) * XPAD;
#pragma unroll
    for (int kk = 0; kk < 8; kk++) {
        int kc = kk * 8 + c;
        a[kk][0] = sxu[ar0 + kc];
        a[kk][1] = sxu[ar1 + kc];
        a[kk][2] = sxu[ar0 + kc + 4];
        a[kk][3] = sxu[ar1 + kc + 4];
    }

    int row0 = rowbase + wid * 16 + r;
#pragma unroll
    for (int mp = 0; mp < MP; mp++) {
        const uint32_t* wp = sWu + mp * 64 * WPAD;
        float d[8][4];
#pragma unroll
        for (int nt = 0; nt < 8; nt++) {
            d[nt][0] = 0.f; d[nt][1] = 0.f; d[nt][2] = 0.f; d[nt][3] = 0.f;
        }
#pragma unroll
        for (int kk = 0; kk < 8; kk++) {
            int kb = (kk * 8 + c) * WPAD + r;
#pragma unroll
            for (int nt = 0; nt < 8; nt++) {
                uint32_t b0 = wp[kb + nt * 8];
                uint32_t b1 = wp[kb + 4 * WPAD + nt * 8];
                asm volatile(
                    "mma.sync.aligned.m16n8k8.row.col.f32.tf32.tf32.f32 "
                    "{%0,%1,%2,%3}, {%4,%5,%6,%7}, {%8,%9}, {%0,%1,%2,%3};"
                    : "+f"(d[nt][0]), "+f"(d[nt][1]), "+f"(d[nt][2]), "+f"(d[nt][3])
                    : "r"(a[kk][0]), "r"(a[kk][1]), "r"(a[kk][2]), "r"(a[kk][3]),
                      "r"(b0), "r"(b1));
            }
        }
        float* hout = mg_h + (size_t)mp * NN * D;
        if (row0 < NN) {
            float2* dst = (float2*)(hout + (size_t)row0 * D);
#pragma unroll
            for (int nt = 0; nt < 8; nt++)
                dst[nt * 4 + c] = make_float2(d[nt][0], d[nt][1]);
        }
        if (row0 + 8 < NN) {
            float2* dst = (float2*)(hout + (size_t)(row0 + 8) * D);
#pragma unroll
            for (int nt = 0; nt < 8; nt++)
                dst[nt * 4 + c] = make_float2(d[nt][2], d[nt][3]);
        }
    }
}

// ---------------------------------------------------------------------------
// Bin edges: NO atomics. pos = off_local[c] + tileoff[c>>11] + rank[e].
// ---------------------------------------------------------------------------
__global__ void mz_fill(const int* __restrict__ ei32,
                        const float* __restrict__ ew) {
    int mp = blockIdx.y;
    int sh = mg_sh;
    size_t rowbase = (size_t)mp * 2 * NE;
    size_t colbase = rowbase + NE;
    const float* ewp = ew + (size_t)mp * NE;
    const float* dinv = mg_deg + (size_t)mp * NN;
    const int* off = mg_off + (size_t)mp * NN;
    const int* toff = mg_tileoff + mp * NT;
    const int* rk = mg_rank + (size_t)mp * NE;
    int2* edges = mg_edge + (size_t)mp * NE;
    int stride = gridDim.x * blockDim.x;
    for (int e = blockIdx.x * blockDim.x + threadIdx.x; e < NE; e += stride) {
        int r = ld_idx(ei32, rowbase + e, sh);
        int c = ld_idx(ei32, colbase + e, sh);
        float nm = dinv[r] * ewp[e] * dinv[c];
        int pos = off[c] + toff[c >> TSH] + rk[e];
        edges[pos] = make_int2(r, __float_as_int(nm));
    }
}

// ---------------------------------------------------------------------------
// Gather: warp per dest node; 4-wide unroll; fused ReLU.
// ---------------------------------------------------------------------------
__global__ __launch_bounds__(256) void mz_gather(float* __restrict__ out,
                                                 int mp) {
    int node = blockIdx.x * 8 + (threadIdx.x >> 5);
    if (node >= NN) return;
    int lane = threadIdx.x & 31;
    const float* h = mg_h + (size_t)mp * NN * D;
    int start = mg_off[(size_t)mp * NN + node] + mg_tileoff[mp * NT + (node >> TSH)];
    int n = mg_count[(size_t)mp * NN + node];
    const int2* edges = mg_edge + (size_t)mp * NE + start;

    float2 acc = make_float2(0.f, 0.f);
    int j = 0;
    for (; j + 4 <= n; j += 4) {
        int2 e0 = edges[j], e1 = edges[j + 1], e2 = edges[j + 2], e3 = edges[j + 3];
        float2 v0 = *(const float2*)(h + (size_t)e0.x * D + lane * 2);
        float2 v1 = *(const float2*)(h + (size_t)e1.x * D + lane * 2);
        float2 v2 = *(const float2*)(h + (size_t)e2.x * D + lane * 2);
        float2 v3 = *(const float2*)(h + (size_t)e3.x * D + lane * 2);
        float n0 = __int_as_float(e0.y), n1 = __int_as_float(e1.y);
        float n2 = __int_as_float(e2.y), n3 = __int_as_float(e3.y);
        acc.x = fmaf(v0.x, n0, acc.x); acc.y = fmaf(v0.y, n0, acc.y);
        acc.x = fmaf(v1.x, n1, acc.x); acc.y = fmaf(v1.y, n1, acc.y);
        acc.x = fmaf(v2.x, n2, acc.x); acc.y = fmaf(v2.y, n2, acc.y);
        acc.x = fmaf(v3.x, n3, acc.x); acc.y = fmaf(v3.y, n3, acc.y);
    }
    for (; j < n; j++) {
        int2 e = edges[j];
        float nm = __int_as_float(e.y);
        float2 v = *(const float2*)(h + (size_t)e.x * D + lane * 2);
        acc.x = fmaf(v.x, nm, acc.x);
        acc.y = fmaf(v.y, nm, acc.y);
    }
    float2 o;
    o.x = fmaxf(acc.x, 0.f);
    o.y = fmaxf(acc.y, 0.f);
    *(float2*)(out + (size_t)mp * NN * D + (size_t)node * D + lane * 2) = o;
}

// ---------------------------------------------------------------------------
extern "C" void kernel_launch(void* const* d_in, const int* in_sizes, int n_in,
                              void* d_out, int out_size) {
    const float* x = (const float*)d_in[0];
    const float* W = (const float*)d_in[1];
    const int* ei32 = (const int*)d_in[2];
    const float* ew = (const float*)d_in[3];
    float* out = (float*)d_out;

    cudaFuncSetAttribute(mz_gemm_mma, cudaFuncAttributeMaxDynamicSharedMemorySize,
                         GEMM_SMEM);

    mz_init<<<(MP * NN + 255) / 256, 256>>>(ei32);            // #1
    mz_hist<<<dim3(512, MP), 256>>>(ei32, ew);                // #2
    mz_scanA<<<dim3(NT, MP), 256>>>();                        // #3
    mz_gemm_mma<<<(NN + 127) / 128, 256, GEMM_SMEM>>>(x, W);  // #4 (profiled)
    mz_scanB<<<MP, 64>>>();                                   // #5
    mz_fill<<<dim3(512, MP), 256>>>(ei32, ew);                // #6
    for (int mp = 0; mp < MP; mp++) {                         // #7-9
        mz_gather<<<(NN + 7) / 8, 256>>>(out, mp);
    }
}

// round 13
// speedup vs baseline: 1.0621x; 1.0621x over previous
#include <cuda_runtime.h>
#include <cstdint>

#define NN 100000
#define NE 1000000
#define D  64
#define MP 3

#define TILE 2048
#define TSH  11
#define NT ((NN + TILE - 1) / TILE)

// Scratch (__device__ globals per allocation-free rule)
__device__ float mg_h[(size_t)MP * NN * D];       // transformed features
__device__ float mg_deg[MP * NN];                 // dinv
__device__ unsigned long long mg_pack[MP * NN];   // count<<44 | fixp deg sum
__device__ int   mg_count[MP * NN];               // edges per dest node
__device__ int   mg_off[MP * NN];                 // tile-LOCAL exclusive offsets
__device__ int   mg_ctr[MP * NN];                 // tile-LOCAL running cursors
__device__ int2  mg_edge[(size_t)MP * NE];        // packed (src row, norm)
__device__ int   mg_tiletot[MP * NT];
__device__ int   mg_tileoff[MP * NT];
__device__ int   mg_sh;                           // 0 = int32 idx, 1 = int64

// ---------------------------------------------------------------------------
// Fused: zero pack; block 0 warp 0 sniffs edge dtype.
// ---------------------------------------------------------------------------
__global__ void mz_init(const int* __restrict__ ei32) {
    int i = blockIdx.x * blockDim.x + threadIdx.x;
    if (i < MP * NN) mg_pack[i] = 0ull;
    if (blockIdx.x == 0 && threadIdx.x < 32) {
        int t = threadIdx.x;
        int nz = 0;
        for (int k = 0; k < 8; k++) {
            int s = (t * 8 + k) * 1009;
            nz |= (ei32[2 * s + 1] != 0);
        }
        unsigned b = __ballot_sync(0xffffffffu, nz);
        if (t == 0) mg_sh = (b == 0u) ? 1 : 0;
    }
}

__device__ __forceinline__ int ld_idx(const int* p, size_t pos, int sh) {
    return p[pos << sh];
}

// ---------------------------------------------------------------------------
// One packed u64 RED per edge (no return): count++ AND deg += ew (2^-24 fixp)
// ---------------------------------------------------------------------------
__global__ void mz_hist(const int* __restrict__ ei32,
                        const float* __restrict__ ew) {
    int mp = blockIdx.y;
    int sh = mg_sh;
    size_t colbase = (size_t)mp * 2 * NE + NE;
    const float* ewp = ew + (size_t)mp * NE;
    unsigned long long* pk = mg_pack + (size_t)mp * NN;
    int stride = gridDim.x * blockDim.x;
    for (int e = blockIdx.x * blockDim.x + threadIdx.x; e < NE; e += stride) {
        int c = ld_idx(ei32, colbase + e, sh);
        unsigned long long frac =
            (unsigned long long)__float2uint_rn(ewp[e] * 16777216.0f);
        atomicAdd(pk + c, (1ull << 44) | frac);
    }
}

// ---------------------------------------------------------------------------
// Phase A of decoupled scan: pack -> (count, dinv); tile-LOCAL off + ctr;
// per-tile totals for later prefix.
// ---------------------------------------------------------------------------
__global__ __launch_bounds__(256) void mz_scanA() {
    __shared__ int wtot[8];
    __shared__ int wpre[8];
    int mp = blockIdx.y;
    int tile = blockIdx.x;
    int t = threadIdx.x;
    int lane = t & 31;
    int warp = t >> 5;
    const unsigned long long* pk = mg_pack + (size_t)mp * NN;
    int* cnt = mg_count + (size_t)mp * NN;
    int* off = mg_off + (size_t)mp * NN;
    int* ctr = mg_ctr + (size_t)mp * NN;
    float* deg = mg_deg + (size_t)mp * NN;

    int base = tile * TILE + t * 8;
    int v[8];
#pragma unroll
    for (int k = 0; k < 8; k++) {
        int i = base + k;
        if (i < NN) {
            unsigned long long p = pk[i];
            int c = (int)(p >> 44);
            float d = (float)(p & ((1ull << 44) - 1)) * (1.0f / 16777216.0f);
            v[k] = c;
            cnt[i] = c;
            deg[i] = (d > 0.f) ? rsqrtf(d) : 0.f;
        } else {
            v[k] = 0;
        }
    }
    int mysum = 0;
#pragma unroll
    for (int k = 0; k < 8; k++) mysum += v[k];

    int inc = mysum;
#pragma unroll
    for (int o = 1; o < 32; o <<= 1) {
        int n = __shfl_up_sync(0xffffffffu, inc, o);
        if (lane >= o) inc += n;
    }
    if (lane == 31) wtot[warp] = inc;
    __syncthreads();
    if (t == 0) {
        int run = 0;
#pragma unroll
        for (int w = 0; w < 8; w++) { wpre[w] = run; run += wtot[w]; }
        mg_tiletot[mp * NT + tile] = run;
    }
    __syncthreads();

    int excl = wpre[warp] + inc - mysum;
#pragma unroll
    for (int k = 0; k < 8; k++) {
        int i = base + k;
        if (i < NN) { off[i] = excl; ctr[i] = excl; }   // tile-LOCAL
        excl += v[k];
    }
}

// Tiny: exclusive scan of NT tile totals per metapath (for gather).
__global__ __launch_bounds__(64) void mz_scanB() {
    __shared__ int s[64];
    int mp = blockIdx.x;
    int t = threadIdx.x;
    s[t] = (t < NT) ? mg_tiletot[mp * NT + t] : 0;
    __syncthreads();
    for (int d2 = 1; d2 < 64; d2 <<= 1) {
        int add = (t >= d2) ? s[t - d2] : 0;
        __syncthreads();
        s[t] += add;
        __syncthreads();
    }
    if (t < NT) mg_tileoff[mp * NT + t] = s[t] - mg_tiletot[mp * NT + t];
}

// ---------------------------------------------------------------------------
// Bin edges: pos = atomic tile-local cursor + in-block tile prefix.
// (scanC eliminated: each block scans the 49 tile totals in smem once.)
// ---------------------------------------------------------------------------
__global__ __launch_bounds__(256) void mz_fill(const int* __restrict__ ei32,
                                               const float* __restrict__ ew) {
    __shared__ int sv[64];
    __shared__ int stoff[64];
    int mp = blockIdx.y;
    int t = threadIdx.x;

    if (t < 64) sv[t] = (t < NT) ? mg_tiletot[mp * NT + t] : 0;
    __syncthreads();
    for (int d2 = 1; d2 < 64; d2 <<= 1) {
        int add = 0;
        if (t < 64 && t >= d2) add = sv[t - d2];
        __syncthreads();
        if (t < 64) sv[t] += add;
        __syncthreads();
    }
    if (t < 64) stoff[t] = (t == 0) ? 0 : sv[t - 1];
    __syncthreads();

    int sh = mg_sh;
    size_t rowbase = (size_t)mp * 2 * NE;
    size_t colbase = rowbase + NE;
    const float* ewp = ew + (size_t)mp * NE;
    const float* dinv = mg_deg + (size_t)mp * NN;
    int* ctr = mg_ctr + (size_t)mp * NN;
    int2* edges = mg_edge + (size_t)mp * NE;
    int stride = gridDim.x * blockDim.x;
    for (int e = blockIdx.x * blockDim.x + t; e < NE; e += stride) {
        int r = ld_idx(ei32, rowbase + e, sh);
        int c = ld_idx(ei32, colbase + e, sh);
        float nm = dinv[r] * ewp[e] * dinv[c];
        int pos = atomicAdd(ctr + c, 1) + stoff[c >> TSH];
        edges[pos] = make_int2(r, __float_as_int(nm));
    }
}

// ---------------------------------------------------------------------------
// GEMM via mma.sync.m16n8k8 tf32 (measured-good R9/R11 configuration).
// ---------------------------------------------------------------------------
#define XPAD 68
#define WPAD 72
#define SX_FLOATS (128 * XPAD)
#define SW_FLOATS (MP * 64 * WPAD)
#define GEMM_SMEM ((SX_FLOATS + SW_FLOATS) * 4)

__device__ __forceinline__ uint32_t f2tf32(float f) {
    uint32_t u;
    asm("cvt.rna.tf32.f32 %0, %1;" : "=r"(u) : "f"(f));
    return u;
}

__global__ __launch_bounds__(256) void mz_gemm_mma(const float* __restrict__ x,
                                                   const float* __restrict__ W) {
    extern __shared__ float smem[];
    float* sx = smem;                 // [128][XPAD]
    float* sW = smem + SX_FLOATS;     // [MP][64][WPAD]
    int t = threadIdx.x;
    int wid = t >> 5;
    int lane = t & 31;
    int rowbase = blockIdx.x * 128;

    const float4* x4 = (const float4*)x;
    for (int i = t; i < 2048; i += 256) {
        int row = i >> 4;
        int q = i & 15;
        float4 v = make_float4(0.f, 0.f, 0.f, 0.f);
        int grow = rowbase + row;
        if (grow < NN) v = x4[(size_t)grow * 16 + q];
        uint4 u = make_uint4(f2tf32(v.x), f2tf32(v.y), f2tf32(v.z), f2tf32(v.w));
        *(uint4*)(sx + row * XPAD + q * 4) = u;
    }
    const float4* W4 = (const float4*)W;
    for (int i = t; i < MP * 64 * 16; i += 256) {
        int mp = i >> 10;
        int rem = i & 1023;
        int k = rem >> 4;
        int q = rem & 15;
        float4 v = W4[i];
        uint4 u = make_uint4(f2tf32(v.x), f2tf32(v.y), f2tf32(v.z), f2tf32(v.w));
        *(uint4*)(sW + mp * 64 * WPAD + k * WPAD + q * 4) = u;
    }
    __syncthreads();

    int r = lane >> 2;
    int c = lane & 3;
    const uint32_t* sxu = (const uint32_t*)sx;
    const uint32_t* sWu = (const uint32_t*)sW;

    uint32_t a[8][4];
    int ar0 = (wid * 16 + r) * XPAD;
    int ar1 = (wid * 16 + r + 8) * XPAD;
#pragma unroll
    for (int kk = 0; kk < 8; kk++) {
        int kc = kk * 8 + c;
        a[kk][0] = sxu[ar0 + kc];
        a[kk][1] = sxu[ar1 + kc];
        a[kk][2] = sxu[ar0 + kc + 4];
        a[kk][3] = sxu[ar1 + kc + 4];
    }

    int row0 = rowbase + wid * 16 + r;
#pragma unroll
    for (int mp = 0; mp < MP; mp++) {
        const uint32_t* wp = sWu + mp * 64 * WPAD;
        float d[8][4];
#pragma unroll
        for (int nt = 0; nt < 8; nt++) {
            d[nt][0] = 0.f; d[nt][1] = 0.f; d[nt][2] = 0.f; d[nt][3] = 0.f;
        }
#pragma unroll
        for (int kk = 0; kk < 8; kk++) {
            int kb = (kk * 8 + c) * WPAD + r;
#pragma unroll
            for (int nt = 0; nt < 8; nt++) {
                uint32_t b0 = wp[kb + nt * 8];
                uint32_t b1 = wp[kb + 4 * WPAD + nt * 8];
                asm volatile(
                    "mma.sync.aligned.m16n8k8.row.col.f32.tf32.tf32.f32 "
                    "{%0,%1,%2,%3}, {%4,%5,%6,%7}, {%8,%9}, {%0,%1,%2,%3};"
                    : "+f"(d[nt][0]), "+f"(d[nt][1]), "+f"(d[nt][2]), "+f"(d[nt][3])
                    : "r"(a[kk][0]), "r"(a[kk][1]), "r"(a[kk][2]), "r"(a[kk][3]),
                      "r"(b0), "r"(b1));
            }
        }
        float* hout = mg_h + (size_t)mp * NN * D;
        if (row0 < NN) {
            float2* dst = (float2*)(hout + (size_t)row0 * D);
#pragma unroll
            for (int nt = 0; nt < 8; nt++)
                dst[nt * 4 + c] = make_float2(d[nt][0], d[nt][1]);
        }
        if (row0 + 8 < NN) {
            float2* dst = (float2*)(hout + (size_t)(row0 + 8) * D);
#pragma unroll
            for (int nt = 0; nt < 8; nt++)
                dst[nt * 4 + c] = make_float2(d[nt][2], d[nt][3]);
        }
    }
}

// ---------------------------------------------------------------------------
// Gather: warp per dest node; 4-wide unroll; fused ReLU.
// ---------------------------------------------------------------------------
__global__ __launch_bounds__(256) void mz_gather(float* __restrict__ out,
                                                 int mp) {
    int node = blockIdx.x * 8 + (threadIdx.x >> 5);
    if (node >= NN) return;
    int lane = threadIdx.x & 31;
    const float* h = mg_h + (size_t)mp * NN * D;
    int start = mg_off[(size_t)mp * NN + node] + mg_tileoff[mp * NT + (node >> TSH)];
    int n = mg_count[(size_t)mp * NN + node];
    const int2* edges = mg_edge + (size_t)mp * NE + start;

    float2 acc = make_float2(0.f, 0.f);
    int j = 0;
    for (; j + 4 <= n; j += 4) {
        int2 e0 = edges[j], e1 = edges[j + 1], e2 = edges[j + 2], e3 = edges[j + 3];
        float2 v0 = *(const float2*)(h + (size_t)e0.x * D + lane * 2);
        float2 v1 = *(const float2*)(h + (size_t)e1.x * D + lane * 2);
        float2 v2 = *(const float2*)(h + (size_t)e2.x * D + lane * 2);
        float2 v3 = *(const float2*)(h + (size_t)e3.x * D + lane * 2);
        float n0 = __int_as_float(e0.y), n1 = __int_as_float(e1.y);
        float n2 = __int_as_float(e2.y), n3 = __int_as_float(e3.y);
        acc.x = fmaf(v0.x, n0, acc.x); acc.y = fmaf(v0.y, n0, acc.y);
        acc.x = fmaf(v1.x, n1, acc.x); acc.y = fmaf(v1.y, n1, acc.y);
        acc.x = fmaf(v2.x, n2, acc.x); acc.y = fmaf(v2.y, n2, acc.y);
        acc.x = fmaf(v3.x, n3, acc.x); acc.y = fmaf(v3.y, n3, acc.y);
    }
    for (; j < n; j++) {
        int2 e = edges[j];
        float nm = __int_as_float(e.y);
        float2 v = *(const float2*)(h + (size_t)e.x * D + lane * 2);
        acc.x = fmaf(v.x, nm, acc.x);
        acc.y = fmaf(v.y, nm, acc.y);
    }
    float2 o;
    o.x = fmaxf(acc.x, 0.f);
    o.y = fmaxf(acc.y, 0.f);
    *(float2*)(out + (size_t)mp * NN * D + (size_t)node * D + lane * 2) = o;
}

// ---------------------------------------------------------------------------
extern "C" void kernel_launch(void* const* d_in, const int* in_sizes, int n_in,
                              void* d_out, int out_size) {
    const float* x = (const float*)d_in[0];
    const float* W = (const float*)d_in[1];
    const int* ei32 = (const int*)d_in[2];
    const float* ew = (const float*)d_in[3];
    float* out = (float*)d_out;

    cudaFuncSetAttribute(mz_gemm_mma, cudaFuncAttributeMaxDynamicSharedMemorySize,
                         GEMM_SMEM);

    mz_init<<<(MP * NN + 255) / 256, 256>>>(ei32);            // #1
    mz_hist<<<dim3(512, MP), 256>>>(ei32, ew);                // #2
    mz_scanA<<<dim3(NT, MP), 256>>>();                        // #3
    mz_fill<<<dim3(512, MP), 256>>>(ei32, ew);                // #4 (profiled)
    mz_scanB<<<MP, 64>>>();                                   // #5
    mz_gemm_mma<<<(NN + 127) / 128, 256, GEMM_SMEM>>>(x, W);  // #6
    for (int mp = 0; mp < MP; mp++) {                         // #7-9
        mz_gather<<<(NN + 7) / 8, 256>>>(out, mp);
    }
}

// round 14
// speedup vs baseline: 1.1203x; 1.0548x over previous
#include <cuda_runtime.h>
#include <cuda_fp16.h>
#include <cstdint>

#define NN 100000
#define NE 1000000
#define D  64
#define MP 3

#define TILE 2048
#define TSH  11
#define NT ((NN + TILE - 1) / TILE)

// Scratch (__device__ globals per allocation-free rule)
__device__ uint32_t mg_hh[(size_t)MP * NN * 32]; // h * dinv[row], half2-packed
__device__ float mg_deg[MP * NN];                 // dinv
__device__ unsigned long long mg_pack[MP * NN];   // count<<44 | fixp deg sum
__device__ int   mg_count[MP * NN];               // edges per dest node
__device__ int   mg_off[MP * NN];                 // tile-LOCAL exclusive offsets
__device__ int   mg_ctr[MP * NN];                 // tile-LOCAL running cursors
__device__ int2  mg_edge[(size_t)MP * NE];        // packed (src row, ew bits)
__device__ int   mg_tiletot[MP * NT];
__device__ int   mg_tileoff[MP * NT];
__device__ int   mg_sh;                           // 0 = int32 idx, 1 = int64

// ---------------------------------------------------------------------------
// Fused: zero pack; block 0 warp 0 sniffs edge dtype.
// ---------------------------------------------------------------------------
__global__ void mz_init(const int* __restrict__ ei32) {
    int i = blockIdx.x * blockDim.x + threadIdx.x;
    if (i < MP * NN) mg_pack[i] = 0ull;
    if (blockIdx.x == 0 && threadIdx.x < 32) {
        int t = threadIdx.x;
        int nz = 0;
        for (int k = 0; k < 8; k++) {
            int s = (t * 8 + k) * 1009;
            nz |= (ei32[2 * s + 1] != 0);
        }
        unsigned b = __ballot_sync(0xffffffffu, nz);
        if (t == 0) mg_sh = (b == 0u) ? 1 : 0;
    }
}

__device__ __forceinline__ int ld_idx(const int* p, size_t pos, int sh) {
    return p[pos << sh];
}

// ---------------------------------------------------------------------------
// One packed u64 RED per edge (no return): count++ AND deg += ew (2^-24 fixp)
// ---------------------------------------------------------------------------
__global__ void mz_hist(const int* __restrict__ ei32,
                        const float* __restrict__ ew) {
    int mp = blockIdx.y;
    int sh = mg_sh;
    size_t colbase = (size_t)mp * 2 * NE + NE;
    const float* ewp = ew + (size_t)mp * NE;
    unsigned long long* pk = mg_pack + (size_t)mp * NN;
    int stride = gridDim.x * blockDim.x;
    for (int e = blockIdx.x * blockDim.x + threadIdx.x; e < NE; e += stride) {
        int c = ld_idx(ei32, colbase + e, sh);
        unsigned long long frac =
            (unsigned long long)__float2uint_rn(ewp[e] * 16777216.0f);
        atomicAdd(pk + c, (1ull << 44) | frac);
    }
}

// ---------------------------------------------------------------------------
// Phase A: pack -> (count, dinv); tile-LOCAL off + ctr; per-tile totals.
// ---------------------------------------------------------------------------
__global__ __launch_bounds__(256) void mz_scanA() {
    __shared__ int wtot[8];
    __shared__ int wpre[8];
    int mp = blockIdx.y;
    int tile = blockIdx.x;
    int t = threadIdx.x;
    int lane = t & 31;
    int warp = t >> 5;
    const unsigned long long* pk = mg_pack + (size_t)mp * NN;
    int* cnt = mg_count + (size_t)mp * NN;
    int* off = mg_off + (size_t)mp * NN;
    int* ctr = mg_ctr + (size_t)mp * NN;
    float* deg = mg_deg + (size_t)mp * NN;

    int base = tile * TILE + t * 8;
    int v[8];
#pragma unroll
    for (int k = 0; k < 8; k++) {
        int i = base + k;
        if (i < NN) {
            unsigned long long p = pk[i];
            int c = (int)(p >> 44);
            float d = (float)(p & ((1ull << 44) - 1)) * (1.0f / 16777216.0f);
            v[k] = c;
            cnt[i] = c;
            deg[i] = (d > 0.f) ? rsqrtf(d) : 0.f;
        } else {
            v[k] = 0;
        }
    }
    int mysum = 0;
#pragma unroll
    for (int k = 0; k < 8; k++) mysum += v[k];

    int inc = mysum;
#pragma unroll
    for (int o = 1; o < 32; o <<= 1) {
        int n = __shfl_up_sync(0xffffffffu, inc, o);
        if (lane >= o) inc += n;
    }
    if (lane == 31) wtot[warp] = inc;
    __syncthreads();
    if (t == 0) {
        int run = 0;
#pragma unroll
        for (int w = 0; w < 8; w++) { wpre[w] = run; run += wtot[w]; }
        mg_tiletot[mp * NT + tile] = run;
    }
    __syncthreads();

    int excl = wpre[warp] + inc - mysum;
#pragma unroll
    for (int k = 0; k < 8; k++) {
        int i = base + k;
        if (i < NN) { off[i] = excl; ctr[i] = excl; }   // tile-LOCAL
        excl += v[k];
    }
}

// Tiny: exclusive scan of NT tile totals per metapath (for gather).
__global__ __launch_bounds__(64) void mz_scanB() {
    __shared__ int s[64];
    int mp = blockIdx.x;
    int t = threadIdx.x;
    s[t] = (t < NT) ? mg_tiletot[mp * NT + t] : 0;
    __syncthreads();
    for (int d2 = 1; d2 < 64; d2 <<= 1) {
        int add = (t >= d2) ? s[t - d2] : 0;
        __syncthreads();
        s[t] += add;
        __syncthreads();
    }
    if (t < NT) mg_tileoff[mp * NT + t] = s[t] - mg_tiletot[mp * NT + t];
}

// ---------------------------------------------------------------------------
// Bin edges: (r, ew) only — NO dinv reads (dinv folded into h and gather).
// pos = atomic tile-local cursor + in-block tile prefix.
// ---------------------------------------------------------------------------
__global__ __launch_bounds__(256) void mz_fill(const int* __restrict__ ei32,
                                               const float* __restrict__ ew) {
    __shared__ int sv[64];
    __shared__ int stoff[64];
    int mp = blockIdx.y;
    int t = threadIdx.x;

    if (t < 64) sv[t] = (t < NT) ? mg_tiletot[mp * NT + t] : 0;
    __syncthreads();
    for (int d2 = 1; d2 < 64; d2 <<= 1) {
        int add = 0;
        if (t < 64 && t >= d2) add = sv[t - d2];
        __syncthreads();
        if (t < 64) sv[t] += add;
        __syncthreads();
    }
    if (t < 64) stoff[t] = (t == 0) ? 0 : sv[t - 1];
    __syncthreads();

    int sh = mg_sh;
    size_t rowbase = (size_t)mp * 2 * NE;
    size_t colbase = rowbase + NE;
    const float* ewp = ew + (size_t)mp * NE;
    int* ctr = mg_ctr + (size_t)mp * NN;
    int2* edges = mg_edge + (size_t)mp * NE;
    int stride = gridDim.x * blockDim.x;
    for (int e = blockIdx.x * blockDim.x + t; e < NE; e += stride) {
        int r = ld_idx(ei32, rowbase + e, sh);
        int c = ld_idx(ei32, colbase + e, sh);
        float w = ewp[e];
        int pos = atomicAdd(ctr + c, 1) + stoff[c >> TSH];
        edges[pos] = make_int2(r, __float_as_int(w));
    }
}

// ---------------------------------------------------------------------------
// GEMM via mma.sync.m16n8k8 tf32; epilogue scales by dinv[row] and packs
// to half2 (halves gather's h traffic).
// ---------------------------------------------------------------------------
#define XPAD 68
#define WPAD 72
#define SX_FLOATS (128 * XPAD)
#define SW_FLOATS (MP * 64 * WPAD)
#define GEMM_SMEM ((SX_FLOATS + SW_FLOATS) * 4)

__device__ __forceinline__ uint32_t f2tf32(float f) {
    uint32_t u;
    asm("cvt.rna.tf32.f32 %0, %1;" : "=r"(u) : "f"(f));
    return u;
}

__global__ __launch_bounds__(256) void mz_gemm_mma(const float* __restrict__ x,
                                                   const float* __restrict__ W) {
    extern __shared__ float smem[];
    float* sx = smem;                 // [128][XPAD]
    float* sW = smem + SX_FLOATS;     // [MP][64][WPAD]
    int t = threadIdx.x;
    int wid = t >> 5;
    int lane = t & 31;
    int rowbase = blockIdx.x * 128;

    const float4* x4 = (const float4*)x;
    for (int i = t; i < 2048; i += 256) {
        int row = i >> 4;
        int q = i & 15;
        float4 v = make_float4(0.f, 0.f, 0.f, 0.f);
        int grow = rowbase + row;
        if (grow < NN) v = x4[(size_t)grow * 16 + q];
        uint4 u = make_uint4(f2tf32(v.x), f2tf32(v.y), f2tf32(v.z), f2tf32(v.w));
        *(uint4*)(sx + row * XPAD + q * 4) = u;
    }
    const float4* W4 = (const float4*)W;
    for (int i = t; i < MP * 64 * 16; i += 256) {
        int mp = i >> 10;
        int rem = i & 1023;
        int k = rem >> 4;
        int q = rem & 15;
        float4 v = W4[i];
        uint4 u = make_uint4(f2tf32(v.x), f2tf32(v.y), f2tf32(v.z), f2tf32(v.w));
        *(uint4*)(sW + mp * 64 * WPAD + k * WPAD + q * 4) = u;
    }
    __syncthreads();

    int r = lane >> 2;
    int c = lane & 3;
    const uint32_t* sxu = (const uint32_t*)sx;
    const uint32_t* sWu = (const uint32_t*)sW;

    uint32_t a[8][4];
    int ar0 = (wid * 16 + r) * XPAD;
    int ar1 = (wid * 16 + r + 8) * XPAD;
#pragma unroll
    for (int kk = 0; kk < 8; kk++) {
        int kc = kk * 8 + c;
        a[kk][0] = sxu[ar0 + kc];
        a[kk][1] = sxu[ar1 + kc];
        a[kk][2] = sxu[ar0 + kc + 4];
        a[kk][3] = sxu[ar1 + kc + 4];
    }

    int row0 = rowbase + wid * 16 + r;
#pragma unroll
    for (int mp = 0; mp < MP; mp++) {
        const uint32_t* wp = sWu + mp * 64 * WPAD;
        float d[8][4];
#pragma unroll
        for (int nt = 0; nt < 8; nt++) {
            d[nt][0] = 0.f; d[nt][1] = 0.f; d[nt][2] = 0.f; d[nt][3] = 0.f;
        }
#pragma unroll
        for (int kk = 0; kk < 8; kk++) {
            int kb = (kk * 8 + c) * WPAD + r;
#pragma unroll
            for (int nt = 0; nt < 8; nt++) {
                uint32_t b0 = wp[kb + nt * 8];
                uint32_t b1 = wp[kb + 4 * WPAD + nt * 8];
                asm volatile(
                    "mma.sync.aligned.m16n8k8.row.col.f32.tf32.tf32.f32 "
                    "{%0,%1,%2,%3}, {%4,%5,%6,%7}, {%8,%9}, {%0,%1,%2,%3};"
                    : "+f"(d[nt][0]), "+f"(d[nt][1]), "+f"(d[nt][2]), "+f"(d[nt][3])
                    : "r"(a[kk][0]), "r"(a[kk][1]), "r"(a[kk][2]), "r"(a[kk][3]),
                      "r"(b0), "r"(b1));
            }
        }
        uint32_t* hout = mg_hh + (size_t)mp * NN * 32;
        const float* dinv = mg_deg + (size_t)mp * NN;
        if (row0 < NN) {
            float dv = dinv[row0];
            uint32_t* dst = hout + (size_t)row0 * 32;
#pragma unroll
            for (int nt = 0; nt < 8; nt++) {
                __half2 hv = __floats2half2_rn(d[nt][0] * dv, d[nt][1] * dv);
                dst[nt * 4 + c] = *(uint32_t*)&hv;
            }
        }
        if (row0 + 8 < NN) {
            float dv = dinv[row0 + 8];
            uint32_t* dst = hout + (size_t)(row0 + 8) * 32;
#pragma unroll
            for (int nt = 0; nt < 8; nt++) {
                __half2 hv = __floats2half2_rn(d[nt][2] * dv, d[nt][3] * dv);
                dst[nt * 4 + c] = *(uint32_t*)&hv;
            }
        }
    }
}

// ---------------------------------------------------------------------------
// Gather: warp per dest node; half2 h rows (4B/lane); final dinv[node] scale;
// fused ReLU.
// ---------------------------------------------------------------------------
__global__ __launch_bounds__(256) void mz_gather(float* __restrict__ out,
                                                 int mp) {
    int node = blockIdx.x * 8 + (threadIdx.x >> 5);
    if (node >= NN) return;
    int lane = threadIdx.x & 31;
    const uint32_t* hw = mg_hh + (size_t)mp * NN * 32;
    int start = mg_off[(size_t)mp * NN + node] + mg_tileoff[mp * NT + (node >> TSH)];
    int n = mg_count[(size_t)mp * NN + node];
    float dc = mg_deg[(size_t)mp * NN + node];
    const int2* edges = mg_edge + (size_t)mp * NE + start;

    float2 acc = make_float2(0.f, 0.f);
    int j = 0;
    for (; j + 4 <= n; j += 4) {
        int2 e0 = edges[j], e1 = edges[j + 1], e2 = edges[j + 2], e3 = edges[j + 3];
        uint32_t w0 = hw[(size_t)e0.x * 32 + lane];
        uint32_t w1 = hw[(size_t)e1.x * 32 + lane];
        uint32_t w2 = hw[(size_t)e2.x * 32 + lane];
        uint32_t w3 = hw[(size_t)e3.x * 32 + lane];
        float2 v0 = __half22float2(*(__half2*)&w0);
        float2 v1 = __half22float2(*(__half2*)&w1);
        float2 v2 = __half22float2(*(__half2*)&w2);
        float2 v3 = __half22float2(*(__half2*)&w3);
        float n0 = __int_as_float(e0.y), n1 = __int_as_float(e1.y);
        float n2 = __int_as_float(e2.y), n3 = __int_as_float(e3.y);
        acc.x = fmaf(v0.x, n0, acc.x); acc.y = fmaf(v0.y, n0, acc.y);
        acc.x = fmaf(v1.x, n1, acc.x); acc.y = fmaf(v1.y, n1, acc.y);
        acc.x = fmaf(v2.x, n2, acc.x); acc.y = fmaf(v2.y, n2, acc.y);
        acc.x = fmaf(v3.x, n3, acc.x); acc.y = fmaf(v3.y, n3, acc.y);
    }
    for (; j < n; j++) {
        int2 e = edges[j];
        uint32_t w = hw[(size_t)e.x * 32 + lane];
        float2 v = __half22float2(*(__half2*)&w);
        float nm = __int_as_float(e.y);
        acc.x = fmaf(v.x, nm, acc.x);
        acc.y = fmaf(v.y, nm, acc.y);
    }
    float2 o;
    o.x = fmaxf(acc.x * dc, 0.f);
    o.y = fmaxf(acc.y * dc, 0.f);
    *(float2*)(out + (size_t)mp * NN * D + (size_t)node * D + lane * 2) = o;
}

// ---------------------------------------------------------------------------
extern "C" void kernel_launch(void* const* d_in, const int* in_sizes, int n_in,
                              void* d_out, int out_size) {
    const float* x = (const float*)d_in[0];
    const float* W = (const float*)d_in[1];
    const int* ei32 = (const int*)d_in[2];
    const float* ew = (const float*)d_in[3];
    float* out = (float*)d_out;

    cudaFuncSetAttribute(mz_gemm_mma, cudaFuncAttributeMaxDynamicSharedMemorySize,
                         GEMM_SMEM);

    mz_init<<<(MP * NN + 255) / 256, 256>>>(ei32);            // #1
    mz_hist<<<dim3(512, MP), 256>>>(ei32, ew);                // #2
    mz_scanA<<<dim3(NT, MP), 256>>>();                        // #3
    mz_fill<<<dim3(512, MP), 256>>>(ei32, ew);                // #4 (profiled)
    mz_scanB<<<MP, 64>>>();                                   // #5
    mz_gemm_mma<<<(NN + 127) / 128, 256, GEMM_SMEM>>>(x, W);  // #6
    for (int mp = 0; mp < MP; mp++) {                         // #7-9
        mz_gather<<<(NN + 7) / 8, 256>>>(out, mp);
    }
}

// round 15
// speedup vs baseline: 1.1824x; 1.0554x over previous
#include <cuda_runtime.h>
#include <cuda_fp16.h>
#include <cstdint>

#define NN 100000
#define NE 1000000
#define D  64
#define MP 3

#define TILE 2048
#define TSH  11
#define NT ((NN + TILE - 1) / TILE)

// Scratch (__device__ globals per allocation-free rule)
__device__ uint32_t mg_hh[(size_t)MP * NN * 32]; // h * dinv[row], half2-packed
__device__ float mg_deg[MP * NN];                 // dinv
__device__ unsigned long long mg_pack[MP * NN];   // count<<44 | fixp deg sum
__device__ int   mg_count[MP * NN];               // edges per dest node
__device__ int   mg_off[MP * NN];                 // tile-LOCAL exclusive offsets
__device__ int   mg_ctr[MP * NN];                 // tile-LOCAL running cursors
__device__ unsigned mg_edge[(size_t)MP * NE];     // r[0:17) | ew_q15 << 17
__device__ int   mg_tiletot[MP * NT];
__device__ int   mg_tileoff[MP * NT];
__device__ int   mg_sh;                           // 0 = int32 idx, 1 = int64

// ---------------------------------------------------------------------------
__global__ void mz_init(const int* __restrict__ ei32) {
    int i = blockIdx.x * blockDim.x + threadIdx.x;
    if (i < MP * NN) mg_pack[i] = 0ull;
    if (blockIdx.x == 0 && threadIdx.x < 32) {
        int t = threadIdx.x;
        int nz = 0;
        for (int k = 0; k < 8; k++) {
            int s = (t * 8 + k) * 1009;
            nz |= (ei32[2 * s + 1] != 0);
        }
        unsigned b = __ballot_sync(0xffffffffu, nz);
        if (t == 0) mg_sh = (b == 0u) ? 1 : 0;
    }
}

__device__ __forceinline__ int ld_idx(const int* p, size_t pos, int sh) {
    return p[pos << sh];
}

// ---------------------------------------------------------------------------
// One packed u64 RED per edge (no return): count++ AND deg += ew (2^-24 fixp)
// ---------------------------------------------------------------------------
__global__ void mz_hist(const int* __restrict__ ei32,
                        const float* __restrict__ ew) {
    int mp = blockIdx.y;
    int sh = mg_sh;
    size_t colbase = (size_t)mp * 2 * NE + NE;
    const float* ewp = ew + (size_t)mp * NE;
    unsigned long long* pk = mg_pack + (size_t)mp * NN;
    int stride = gridDim.x * blockDim.x;
    for (int e = blockIdx.x * blockDim.x + threadIdx.x; e < NE; e += stride) {
        int c = ld_idx(ei32, colbase + e, sh);
        unsigned long long frac =
            (unsigned long long)__float2uint_rn(ewp[e] * 16777216.0f);
        atomicAdd(pk + c, (1ull << 44) | frac);
    }
}

// ---------------------------------------------------------------------------
// Phase A: pack -> (count, dinv); tile-LOCAL off + ctr; per-tile totals.
// ---------------------------------------------------------------------------
__global__ __launch_bounds__(256) void mz_scanA() {
    __shared__ int wtot[8];
    __shared__ int wpre[8];
    int mp = blockIdx.y;
    int tile = blockIdx.x;
    int t = threadIdx.x;
    int lane = t & 31;
    int warp = t >> 5;
    const unsigned long long* pk = mg_pack + (size_t)mp * NN;
    int* cnt = mg_count + (size_t)mp * NN;
    int* off = mg_off + (size_t)mp * NN;
    int* ctr = mg_ctr + (size_t)mp * NN;
    float* deg = mg_deg + (size_t)mp * NN;

    int base = tile * TILE + t * 8;
    int v[8];
#pragma unroll
    for (int k = 0; k < 8; k++) {
        int i = base + k;
        if (i < NN) {
            unsigned long long p = pk[i];
            int c = (int)(p >> 44);
            float d = (float)(p & ((1ull << 44) - 1)) * (1.0f / 16777216.0f);
            v[k] = c;
            cnt[i] = c;
            deg[i] = (d > 0.f) ? rsqrtf(d) : 0.f;
        } else {
            v[k] = 0;
        }
    }
    int mysum = 0;
#pragma unroll
    for (int k = 0; k < 8; k++) mysum += v[k];

    int inc = mysum;
#pragma unroll
    for (int o = 1; o < 32; o <<= 1) {
        int n = __shfl_up_sync(0xffffffffu, inc, o);
        if (lane >= o) inc += n;
    }
    if (lane == 31) wtot[warp] = inc;
    __syncthreads();
    if (t == 0) {
        int run = 0;
#pragma unroll
        for (int w = 0; w < 8; w++) { wpre[w] = run; run += wtot[w]; }
        mg_tiletot[mp * NT + tile] = run;
    }
    __syncthreads();

    int excl = wpre[warp] + inc - mysum;
#pragma unroll
    for (int k = 0; k < 8; k++) {
        int i = base + k;
        if (i < NN) { off[i] = excl; ctr[i] = excl; }   // tile-LOCAL
        excl += v[k];
    }
}

// Tiny: exclusive scan of NT tile totals per metapath (for gather).
__global__ __launch_bounds__(64) void mz_scanB() {
    __shared__ int s[64];
    int mp = blockIdx.x;
    int t = threadIdx.x;
    s[t] = (t < NT) ? mg_tiletot[mp * NT + t] : 0;
    __syncthreads();
    for (int d2 = 1; d2 < 64; d2 <<= 1) {
        int add = (t >= d2) ? s[t - d2] : 0;
        __syncthreads();
        s[t] += add;
        __syncthreads();
    }
    if (t < NT) mg_tileoff[mp * NT + t] = s[t] - mg_tiletot[mp * NT + t];
}

// ---------------------------------------------------------------------------
// Bin edges: 4-byte records (r | ew_q15<<17). No dinv reads.
// pos = atomic tile-local cursor + in-block tile prefix.
// ---------------------------------------------------------------------------
__global__ __launch_bounds__(256) void mz_fill(const int* __restrict__ ei32,
                                               const float* __restrict__ ew) {
    __shared__ int sv[64];
    __shared__ int stoff[64];
    int mp = blockIdx.y;
    int t = threadIdx.x;

    if (t < 64) sv[t] = (t < NT) ? mg_tiletot[mp * NT + t] : 0;
    __syncthreads();
    for (int d2 = 1; d2 < 64; d2 <<= 1) {
        int add = 0;
        if (t < 64 && t >= d2) add = sv[t - d2];
        __syncthreads();
        if (t < 64) sv[t] += add;
        __syncthreads();
    }
    if (t < 64) stoff[t] = (t == 0) ? 0 : sv[t - 1];
    __syncthreads();

    int sh = mg_sh;
    size_t rowbase = (size_t)mp * 2 * NE;
    size_t colbase = rowbase + NE;
    const float* ewp = ew + (size_t)mp * NE;
    int* ctr = mg_ctr + (size_t)mp * NN;
    unsigned* edges = mg_edge + (size_t)mp * NE;
    int stride = gridDim.x * blockDim.x;
    for (int e = blockIdx.x * blockDim.x + t; e < NE; e += stride) {
        int r = ld_idx(ei32, rowbase + e, sh);
        int c = ld_idx(ei32, colbase + e, sh);
        unsigned q = __float2uint_rn(ewp[e] * 32767.0f);
        int pos = atomicAdd(ctr + c, 1) + stoff[c >> TSH];
        edges[pos] = (unsigned)r | (q << 17);
    }
}

// ---------------------------------------------------------------------------
// GEMM via mma.sync.m16n8k8 tf32; epilogue scales by dinv[row], packs half2.
// Runs on a forked stream, overlapped with mz_fill.
// ---------------------------------------------------------------------------
#define XPAD 68
#define WPAD 72
#define SX_FLOATS (128 * XPAD)
#define SW_FLOATS (MP * 64 * WPAD)
#define GEMM_SMEM ((SX_FLOATS + SW_FLOATS) * 4)

__device__ __forceinline__ uint32_t f2tf32(float f) {
    uint32_t u;
    asm("cvt.rna.tf32.f32 %0, %1;" : "=r"(u) : "f"(f));
    return u;
}

__global__ __launch_bounds__(256) void mz_gemm_mma(const float* __restrict__ x,
                                                   const float* __restrict__ W) {
    extern __shared__ float smem[];
    float* sx = smem;                 // [128][XPAD]
    float* sW = smem + SX_FLOATS;     // [MP][64][WPAD]
    int t = threadIdx.x;
    int wid = t >> 5;
    int lane = t & 31;
    int rowbase = blockIdx.x * 128;

    const float4* x4 = (const float4*)x;
    for (int i = t; i < 2048; i += 256) {
        int row = i >> 4;
        int q = i & 15;
        float4 v = make_float4(0.f, 0.f, 0.f, 0.f);
        int grow = rowbase + row;
        if (grow < NN) v = x4[(size_t)grow * 16 + q];
        uint4 u = make_uint4(f2tf32(v.x), f2tf32(v.y), f2tf32(v.z), f2tf32(v.w));
        *(uint4*)(sx + row * XPAD + q * 4) = u;
    }
    const float4* W4 = (const float4*)W;
    for (int i = t; i < MP * 64 * 16; i += 256) {
        int mp = i >> 10;
        int rem = i & 1023;
        int k = rem >> 4;
        int q = rem & 15;
        float4 v = W4[i];
        uint4 u = make_uint4(f2tf32(v.x), f2tf32(v.y), f2tf32(v.z), f2tf32(v.w));
        *(uint4*)(sW + mp * 64 * WPAD + k * WPAD + q * 4) = u;
    }
    __syncthreads();

    int r = lane >> 2;
    int c = lane & 3;
    const uint32_t* sxu = (const uint32_t*)sx;
    const uint32_t* sWu = (const uint32_t*)sW;

    uint32_t a[8][4];
    int ar0 = (wid * 16 + r) * XPAD;
    int ar1 = (wid * 16 + r + 8) * XPAD;
#pragma unroll
    for (int kk = 0; kk < 8; kk++) {
        int kc = kk * 8 + c;
        a[kk][0] = sxu[ar0 + kc];
        a[kk][1] = sxu[ar1 + kc];
        a[kk][2] = sxu[ar0 + kc + 4];
        a[kk][3] = sxu[ar1 + kc + 4];
    }

    int row0 = rowbase + wid * 16 + r;
#pragma unroll
    for (int mp = 0; mp < MP; mp++) {
        const uint32_t* wp = sWu + mp * 64 * WPAD;
        float d[8][4];
#pragma unroll
        for (int nt = 0; nt < 8; nt++) {
            d[nt][0] = 0.f; d[nt][1] = 0.f; d[nt][2] = 0.f; d[nt][3] = 0.f;
        }
#pragma unroll
        for (int kk = 0; kk < 8; kk++) {
            int kb = (kk * 8 + c) * WPAD + r;
#pragma unroll
            for (int nt = 0; nt < 8; nt++) {
                uint32_t b0 = wp[kb + nt * 8];
                uint32_t b1 = wp[kb + 4 * WPAD + nt * 8];
                asm volatile(
                    "mma.sync.aligned.m16n8k8.row.col.f32.tf32.tf32.f32 "
                    "{%0,%1,%2,%3}, {%4,%5,%6,%7}, {%8,%9}, {%0,%1,%2,%3};"
                    : "+f"(d[nt][0]), "+f"(d[nt][1]), "+f"(d[nt][2]), "+f"(d[nt][3])
                    : "r"(a[kk][0]), "r"(a[kk][1]), "r"(a[kk][2]), "r"(a[kk][3]),
                      "r"(b0), "r"(b1));
            }
        }
        uint32_t* hout = mg_hh + (size_t)mp * NN * 32;
        const float* dinv = mg_deg + (size_t)mp * NN;
        if (row0 < NN) {
            float dv = dinv[row0];
            uint32_t* dst = hout + (size_t)row0 * 32;
#pragma unroll
            for (int nt = 0; nt < 8; nt++) {
                __half2 hv = __floats2half2_rn(d[nt][0] * dv, d[nt][1] * dv);
                dst[nt * 4 + c] = *(uint32_t*)&hv;
            }
        }
        if (row0 + 8 < NN) {
            float dv = dinv[row0 + 8];
            uint32_t* dst = hout + (size_t)(row0 + 8) * 32;
#pragma unroll
            for (int nt = 0; nt < 8; nt++) {
                __half2 hv = __floats2half2_rn(d[nt][2] * dv, d[nt][3] * dv);
                dst[nt * 4 + c] = *(uint32_t*)&hv;
            }
        }
    }
}

// ---------------------------------------------------------------------------
// Gather: warp per dest node; half2 h rows; 4B edge records; final dinv scale.
// ---------------------------------------------------------------------------
__global__ __launch_bounds__(256) void mz_gather(float* __restrict__ out,
                                                 int mp) {
    int node = blockIdx.x * 8 + (threadIdx.x >> 5);
    if (node >= NN) return;
    int lane = threadIdx.x & 31;
    const uint32_t* hw = mg_hh + (size_t)mp * NN * 32;
    int start = mg_off[(size_t)mp * NN + node] + mg_tileoff[mp * NT + (node >> TSH)];
    int n = mg_count[(size_t)mp * NN + node];
    float dc = mg_deg[(size_t)mp * NN + node];
    const unsigned* edges = mg_edge + (size_t)mp * NE + start;

    const float DQ = 1.0f / 32767.0f;
    float2 acc = make_float2(0.f, 0.f);
    int j = 0;
    for (; j + 4 <= n; j += 4) {
        unsigned e0 = edges[j], e1 = edges[j + 1], e2 = edges[j + 2], e3 = edges[j + 3];
        uint32_t w0 = hw[(size_t)(e0 & 0x1FFFF) * 32 + lane];
        uint32_t w1 = hw[(size_t)(e1 & 0x1FFFF) * 32 + lane];
        uint32_t w2 = hw[(size_t)(e2 & 0x1FFFF) * 32 + lane];
        uint32_t w3 = hw[(size_t)(e3 & 0x1FFFF) * 32 + lane];
        float2 v0 = __half22float2(*(__half2*)&w0);
        float2 v1 = __half22float2(*(__half2*)&w1);
        float2 v2 = __half22float2(*(__half2*)&w2);
        float2 v3 = __half22float2(*(__half2*)&w3);
        float n0 = (float)(e0 >> 17) * DQ;
        float n1 = (float)(e1 >> 17) * DQ;
        float n2 = (float)(e2 >> 17) * DQ;
        float n3 = (float)(e3 >> 17) * DQ;
        acc.x = fmaf(v0.x, n0, acc.x); acc.y = fmaf(v0.y, n0, acc.y);
        acc.x = fmaf(v1.x, n1, acc.x); acc.y = fmaf(v1.y, n1, acc.y);
        acc.x = fmaf(v2.x, n2, acc.x); acc.y = fmaf(v2.y, n2, acc.y);
        acc.x = fmaf(v3.x, n3, acc.x); acc.y = fmaf(v3.y, n3, acc.y);
    }
    for (; j < n; j++) {
        unsigned e = edges[j];
        uint32_t w = hw[(size_t)(e & 0x1FFFF) * 32 + lane];
        float2 v = __half22float2(*(__half2*)&w);
        float nm = (float)(e >> 17) * DQ;
        acc.x = fmaf(v.x, nm, acc.x);
        acc.y = fmaf(v.y, nm, acc.y);
    }
    float2 o;
    o.x = fmaxf(acc.x * dc, 0.f);
    o.y = fmaxf(acc.y * dc, 0.f);
    *(float2*)(out + (size_t)mp * NN * D + (size_t)node * D + lane * 2) = o;
}

// ---------------------------------------------------------------------------
extern "C" void kernel_launch(void* const* d_in, const int* in_sizes, int n_in,
                              void* d_out, int out_size) {
    const float* x = (const float*)d_in[0];
    const float* W = (const float*)d_in[1];
    const int* ei32 = (const int*)d_in[2];
    const float* ew = (const float*)d_in[3];
    float* out = (float*)d_out;

    // One-time resource creation (host-side objects; no device memory).
    static cudaStream_t s2 = nullptr;
    static cudaEvent_t ev0 = nullptr, ev1 = nullptr;
    if (s2 == nullptr) {
        cudaStreamCreateWithFlags(&s2, cudaStreamNonBlocking);
        cudaEventCreateWithFlags(&ev0, cudaEventDisableTiming);
        cudaEventCreateWithFlags(&ev1, cudaEventDisableTiming);
        cudaFuncSetAttribute(mz_gemm_mma,
                             cudaFuncAttributeMaxDynamicSharedMemorySize, GEMM_SMEM);
    }

    mz_init<<<(MP * NN + 255) / 256, 256>>>(ei32);
    mz_hist<<<dim3(512, MP), 256>>>(ei32, ew);
    mz_scanA<<<dim3(NT, MP), 256>>>();

    // Fork: GEMM on s2, overlapped with fill+scanB on the main stream.
    cudaEventRecord(ev0, 0);
    cudaStreamWaitEvent(s2, ev0, 0);
    mz_gemm_mma<<<(NN + 127) / 128, 256, GEMM_SMEM, s2>>>(x, W);
    cudaEventRecord(ev1, s2);

    mz_fill<<<dim3(512, MP), 256>>>(ei32, ew);
    mz_scanB<<<MP, 64>>>();

    // Join: gathers need both fill (main) and GEMM (s2).
    cudaStreamWaitEvent(0, ev1, 0);
    for (int mp = 0; mp < MP; mp++) {
        mz_gather<<<(NN + 7) / 8, 256>>>(out, mp);
    }
}

// round 16
// speedup vs baseline: 1.2245x; 1.0356x over previous
#include <cuda_runtime.h>
#include <cuda_fp16.h>
#include <cstdint>

#define NN 100000
#define NE 1000000
#define D  64
#define MP 3

#define TILE 2048
#define TSH  11
#define NT ((NN + TILE - 1) / TILE)

// Scratch (__device__ globals per allocation-free rule)
__device__ uint32_t mg_hh[(size_t)MP * NN * 32]; // h (fp16x2); scaled in-place
__device__ float mg_deg[MP * NN];                 // dinv
__device__ unsigned long long mg_pack[MP * NN];   // count<<44 | fixp deg sum
__device__ int   mg_count[MP * NN];               // edges per dest node
__device__ int   mg_off[MP * NN];                 // tile-LOCAL exclusive offsets
__device__ int   mg_ctr[MP * NN];                 // tile-LOCAL running cursors
__device__ unsigned mg_edge[(size_t)MP * NE];     // r[0:17) | ew_q15 << 17
__device__ int   mg_tiletot[MP * NT];
__device__ int   mg_tileoff[MP * NT];
__device__ int   mg_sh;                           // 0 = int32 idx, 1 = int64

// ---------------------------------------------------------------------------
__global__ void mz_init(const int* __restrict__ ei32) {
    int i = blockIdx.x * blockDim.x + threadIdx.x;
    if (i < MP * NN) mg_pack[i] = 0ull;
    if (blockIdx.x == 0 && threadIdx.x < 32) {
        int t = threadIdx.x;
        int nz = 0;
        for (int k = 0; k < 8; k++) {
            int s = (t * 8 + k) * 1009;
            nz |= (ei32[2 * s + 1] != 0);
        }
        unsigned b = __ballot_sync(0xffffffffu, nz);
        if (t == 0) mg_sh = (b == 0u) ? 1 : 0;
    }
}

__device__ __forceinline__ int ld_idx(const int* p, size_t pos, int sh) {
    return p[pos << sh];
}

// ---------------------------------------------------------------------------
// One packed u64 RED per edge (no return): count++ AND deg += ew (2^-24 fixp)
// ---------------------------------------------------------------------------
__global__ void mz_hist(const int* __restrict__ ei32,
                        const float* __restrict__ ew) {
    int mp = blockIdx.y;
    int sh = mg_sh;
    size_t colbase = (size_t)mp * 2 * NE + NE;
    const float* ewp = ew + (size_t)mp * NE;
    unsigned long long* pk = mg_pack + (size_t)mp * NN;
    int stride = gridDim.x * blockDim.x;
    for (int e = blockIdx.x * blockDim.x + threadIdx.x; e < NE; e += stride) {
        int c = ld_idx(ei32, colbase + e, sh);
        unsigned long long frac =
            (unsigned long long)__float2uint_rn(ewp[e] * 16777216.0f);
        atomicAdd(pk + c, (1ull << 44) | frac);
    }
}

// ---------------------------------------------------------------------------
// Phase A: pack -> (count, dinv); tile-LOCAL off + ctr; per-tile totals.
// ---------------------------------------------------------------------------
__global__ __launch_bounds__(256) void mz_scanA() {
    __shared__ int wtot[8];
    __shared__ int wpre[8];
    int mp = blockIdx.y;
    int tile = blockIdx.x;
    int t = threadIdx.x;
    int lane = t & 31;
    int warp = t >> 5;
    const unsigned long long* pk = mg_pack + (size_t)mp * NN;
    int* cnt = mg_count + (size_t)mp * NN;
    int* off = mg_off + (size_t)mp * NN;
    int* ctr = mg_ctr + (size_t)mp * NN;
    float* deg = mg_deg + (size_t)mp * NN;

    int base = tile * TILE + t * 8;
    int v[8];
#pragma unroll
    for (int k = 0; k < 8; k++) {
        int i = base + k;
        if (i < NN) {
            unsigned long long p = pk[i];
            int c = (int)(p >> 44);
            float d = (float)(p & ((1ull << 44) - 1)) * (1.0f / 16777216.0f);
            v[k] = c;
            cnt[i] = c;
            deg[i] = (d > 0.f) ? rsqrtf(d) : 0.f;
        } else {
            v[k] = 0;
        }
    }
    int mysum = 0;
#pragma unroll
    for (int k = 0; k < 8; k++) mysum += v[k];

    int inc = mysum;
#pragma unroll
    for (int o = 1; o < 32; o <<= 1) {
        int n = __shfl_up_sync(0xffffffffu, inc, o);
        if (lane >= o) inc += n;
    }
    if (lane == 31) wtot[warp] = inc;
    __syncthreads();
    if (t == 0) {
        int run = 0;
#pragma unroll
        for (int w = 0; w < 8; w++) { wpre[w] = run; run += wtot[w]; }
        mg_tiletot[mp * NT + tile] = run;
    }
    __syncthreads();

    int excl = wpre[warp] + inc - mysum;
#pragma unroll
    for (int k = 0; k < 8; k++) {
        int i = base + k;
        if (i < NN) { off[i] = excl; ctr[i] = excl; }   // tile-LOCAL
        excl += v[k];
    }
}

// Tiny: exclusive scan of NT tile totals per metapath (for gather).
__global__ __launch_bounds__(64) void mz_scanB() {
    __shared__ int s[64];
    int mp = blockIdx.x;
    int t = threadIdx.x;
    s[t] = (t < NT) ? mg_tiletot[mp * NT + t] : 0;
    __syncthreads();
    for (int d2 = 1; d2 < 64; d2 <<= 1) {
        int add = (t >= d2) ? s[t - d2] : 0;
        __syncthreads();
        s[t] += add;
        __syncthreads();
    }
    if (t < NT) mg_tileoff[mp * NT + t] = s[t] - mg_tiletot[mp * NT + t];
}

// ---------------------------------------------------------------------------
// Scale h rows by dinv[row] in place (coalesced; runs on s2 after scanA,
// overlapped with mz_fill). mg_hh[mp][row][32] and mg_deg[mp*NN+row] align:
// for uint4 index i4, the owning row is i4 >> 3.
// ---------------------------------------------------------------------------
__global__ __launch_bounds__(256) void mz_hscale() {
    uint4* h4 = (uint4*)mg_hh;
    const int n4 = MP * NN * 8;           // 32 uint32 = 8 uint4 per row
    int stride = gridDim.x * blockDim.x;
    for (int i = blockIdx.x * blockDim.x + threadIdx.x; i < n4; i += stride) {
        float dv = mg_deg[i >> 3];
        __half2 s2 = __float2half2_rn(dv);
        uint4 v = h4[i];
        __half2* hp = (__half2*)&v;
        hp[0] = __hmul2(hp[0], s2);
        hp[1] = __hmul2(hp[1], s2);
        hp[2] = __hmul2(hp[2], s2);
        hp[3] = __hmul2(hp[3], s2);
        h4[i] = v;
    }
}

// ---------------------------------------------------------------------------
// Bin edges: 4-byte records (r | ew_q15<<17). No dinv reads.
// ---------------------------------------------------------------------------
__global__ __launch_bounds__(256) void mz_fill(const int* __restrict__ ei32,
                                               const float* __restrict__ ew) {
    __shared__ int sv[64];
    __shared__ int stoff[64];
    int mp = blockIdx.y;
    int t = threadIdx.x;

    if (t < 64) sv[t] = (t < NT) ? mg_tiletot[mp * NT + t] : 0;
    __syncthreads();
    for (int d2 = 1; d2 < 64; d2 <<= 1) {
        int add = 0;
        if (t < 64 && t >= d2) add = sv[t - d2];
        __syncthreads();
        if (t < 64) sv[t] += add;
        __syncthreads();
    }
    if (t < 64) stoff[t] = (t == 0) ? 0 : sv[t - 1];
    __syncthreads();

    int sh = mg_sh;
    size_t rowbase = (size_t)mp * 2 * NE;
    size_t colbase = rowbase + NE;
    const float* ewp = ew + (size_t)mp * NE;
    int* ctr = mg_ctr + (size_t)mp * NN;
    unsigned* edges = mg_edge + (size_t)mp * NE;
    int stride = gridDim.x * blockDim.x;
    for (int e = blockIdx.x * blockDim.x + t; e < NE; e += stride) {
        int r = ld_idx(ei32, rowbase + e, sh);
        int c = ld_idx(ei32, colbase + e, sh);
        unsigned q = __float2uint_rn(ewp[e] * 32767.0f);
        int pos = atomicAdd(ctr + c, 1) + stoff[c >> TSH];
        edges[pos] = (unsigned)r | (q << 17);
    }
}

// ---------------------------------------------------------------------------
// GEMM via mma.sync.m16n8k8 tf32; writes UNSCALED fp16 h (no dinv dep →
// forked at t=0, overlapped with init+hist+scanA+fill).
// ---------------------------------------------------------------------------
#define XPAD 68
#define WPAD 72
#define SX_FLOATS (128 * XPAD)
#define SW_FLOATS (MP * 64 * WPAD)
#define GEMM_SMEM ((SX_FLOATS + SW_FLOATS) * 4)

__device__ __forceinline__ uint32_t f2tf32(float f) {
    uint32_t u;
    asm("cvt.rna.tf32.f32 %0, %1;" : "=r"(u) : "f"(f));
    return u;
}

__global__ __launch_bounds__(256) void mz_gemm_mma(const float* __restrict__ x,
                                                   const float* __restrict__ W) {
    extern __shared__ float smem[];
    float* sx = smem;                 // [128][XPAD]
    float* sW = smem + SX_FLOATS;     // [MP][64][WPAD]
    int t = threadIdx.x;
    int wid = t >> 5;
    int lane = t & 31;
    int rowbase = blockIdx.x * 128;

    const float4* x4 = (const float4*)x;
    for (int i = t; i < 2048; i += 256) {
        int row = i >> 4;
        int q = i & 15;
        float4 v = make_float4(0.f, 0.f, 0.f, 0.f);
        int grow = rowbase + row;
        if (grow < NN) v = x4[(size_t)grow * 16 + q];
        uint4 u = make_uint4(f2tf32(v.x), f2tf32(v.y), f2tf32(v.z), f2tf32(v.w));
        *(uint4*)(sx + row * XPAD + q * 4) = u;
    }
    const float4* W4 = (const float4*)W;
    for (int i = t; i < MP * 64 * 16; i += 256) {
        int mp = i >> 10;
        int rem = i & 1023;
        int k = rem >> 4;
        int q = rem & 15;
        float4 v = W4[i];
        uint4 u = make_uint4(f2tf32(v.x), f2tf32(v.y), f2tf32(v.z), f2tf32(v.w));
        *(uint4*)(sW + mp * 64 * WPAD + k * WPAD + q * 4) = u;
    }
    __syncthreads();

    int r = lane >> 2;
    int c = lane & 3;
    const uint32_t* sxu = (const uint32_t*)sx;
    const uint32_t* sWu = (const uint32_t*)sW;

    uint32_t a[8][4];
    int ar0 = (wid * 16 + r) * XPAD;
    int ar1 = (wid * 16 + r + 8) * XPAD;
#pragma unroll
    for (int kk = 0; kk < 8; kk++) {
        int kc = kk * 8 + c;
        a[kk][0] = sxu[ar0 + kc];
        a[kk][1] = sxu[ar1 + kc];
        a[kk][2] = sxu[ar0 + kc + 4];
        a[kk][3] = sxu[ar1 + kc + 4];
    }

    int row0 = rowbase + wid * 16 + r;
#pragma unroll
    for (int mp = 0; mp < MP; mp++) {
        const uint32_t* wp = sWu + mp * 64 * WPAD;
        float d[8][4];
#pragma unroll
        for (int nt = 0; nt < 8; nt++) {
            d[nt][0] = 0.f; d[nt][1] = 0.f; d[nt][2] = 0.f; d[nt][3] = 0.f;
        }
#pragma unroll
        for (int kk = 0; kk < 8; kk++) {
            int kb = (kk * 8 + c) * WPAD + r;
#pragma unroll
            for (int nt = 0; nt < 8; nt++) {
                uint32_t b0 = wp[kb + nt * 8];
                uint32_t b1 = wp[kb + 4 * WPAD + nt * 8];
                asm volatile(
                    "mma.sync.aligned.m16n8k8.row.col.f32.tf32.tf32.f32 "
                    "{%0,%1,%2,%3}, {%4,%5,%6,%7}, {%8,%9}, {%0,%1,%2,%3};"
                    : "+f"(d[nt][0]), "+f"(d[nt][1]), "+f"(d[nt][2]), "+f"(d[nt][3])
                    : "r"(a[kk][0]), "r"(a[kk][1]), "r"(a[kk][2]), "r"(a[kk][3]),
                      "r"(b0), "r"(b1));
            }
        }
        uint32_t* hout = mg_hh + (size_t)mp * NN * 32;
        if (row0 < NN) {
            uint32_t* dst = hout + (size_t)row0 * 32;
#pragma unroll
            for (int nt = 0; nt < 8; nt++) {
                __half2 hv = __floats2half2_rn(d[nt][0], d[nt][1]);
                dst[nt * 4 + c] = *(uint32_t*)&hv;
            }
        }
        if (row0 + 8 < NN) {
            uint32_t* dst = hout + (size_t)(row0 + 8) * 32;
#pragma unroll
            for (int nt = 0; nt < 8; nt++) {
                __half2 hv = __floats2half2_rn(d[nt][2], d[nt][3]);
                dst[nt * 4 + c] = *(uint32_t*)&hv;
            }
        }
    }
}

// ---------------------------------------------------------------------------
// Gather (all metapaths in one launch): warp per dest node; half2 h rows;
// 4B edge records; final dinv[node] scale; fused ReLU.
// ---------------------------------------------------------------------------
__global__ __launch_bounds__(256) void mz_gather(float* __restrict__ out) {
    int mp = blockIdx.y;
    int node = blockIdx.x * 8 + (threadIdx.x >> 5);
    if (node >= NN) return;
    int lane = threadIdx.x & 31;
    const uint32_t* hw = mg_hh + (size_t)mp * NN * 32;
    int start = mg_off[(size_t)mp * NN + node] + mg_tileoff[mp * NT + (node >> TSH)];
    int n = mg_count[(size_t)mp * NN + node];
    float dc = mg_deg[(size_t)mp * NN + node];
    const unsigned* edges = mg_edge + (size_t)mp * NE + start;

    const float DQ = 1.0f / 32767.0f;
    float2 acc = make_float2(0.f, 0.f);
    int j = 0;
    for (; j + 4 <= n; j += 4) {
        unsigned e0 = edges[j], e1 = edges[j + 1], e2 = edges[j + 2], e3 = edges[j + 3];
        uint32_t w0 = hw[(size_t)(e0 & 0x1FFFF) * 32 + lane];
        uint32_t w1 = hw[(size_t)(e1 & 0x1FFFF) * 32 + lane];
        uint32_t w2 = hw[(size_t)(e2 & 0x1FFFF) * 32 + lane];
        uint32_t w3 = hw[(size_t)(e3 & 0x1FFFF) * 32 + lane];
        float2 v0 = __half22float2(*(__half2*)&w0);
        float2 v1 = __half22float2(*(__half2*)&w1);
        float2 v2 = __half22float2(*(__half2*)&w2);
        float2 v3 = __half22float2(*(__half2*)&w3);
        float n0 = (float)(e0 >> 17) * DQ;
        float n1 = (float)(e1 >> 17) * DQ;
        float n2 = (float)(e2 >> 17) * DQ;
        float n3 = (float)(e3 >> 17) * DQ;
        acc.x = fmaf(v0.x, n0, acc.x); acc.y = fmaf(v0.y, n0, acc.y);
        acc.x = fmaf(v1.x, n1, acc.x); acc.y = fmaf(v1.y, n1, acc.y);
        acc.x = fmaf(v2.x, n2, acc.x); acc.y = fmaf(v2.y, n2, acc.y);
        acc.x = fmaf(v3.x, n3, acc.x); acc.y = fmaf(v3.y, n3, acc.y);
    }
    for (; j < n; j++) {
        unsigned e = edges[j];
        uint32_t w = hw[(size_t)(e & 0x1FFFF) * 32 + lane];
        float2 v = __half22float2(*(__half2*)&w);
        float nm = (float)(e >> 17) * DQ;
        acc.x = fmaf(v.x, nm, acc.x);
        acc.y = fmaf(v.y, nm, acc.y);
    }
    float2 o;
    o.x = fmaxf(acc.x * dc, 0.f);
    o.y = fmaxf(acc.y * dc, 0.f);
    *(float2*)(out + (size_t)mp * NN * D + (size_t)node * D + lane * 2) = o;
}

// ---------------------------------------------------------------------------
extern "C" void kernel_launch(void* const* d_in, const int* in_sizes, int n_in,
                              void* d_out, int out_size) {
    const float* x = (const float*)d_in[0];
    const float* W = (const float*)d_in[1];
    const int* ei32 = (const int*)d_in[2];
    const float* ew = (const float*)d_in[3];
    float* out = (float*)d_out;

    // One-time host-side resources (no device memory).
    static cudaStream_t s2 = nullptr;
    static cudaEvent_t ev0 = nullptr, evA = nullptr, ev1 = nullptr;
    if (s2 == nullptr) {
        cudaStreamCreateWithFlags(&s2, cudaStreamNonBlocking);
        cudaEventCreateWithFlags(&ev0, cudaEventDisableTiming);
        cudaEventCreateWithFlags(&evA, cudaEventDisableTiming);
        cudaEventCreateWithFlags(&ev1, cudaEventDisableTiming);
        cudaFuncSetAttribute(mz_gemm_mma,
                             cudaFuncAttributeMaxDynamicSharedMemorySize, GEMM_SMEM);
    }

    // Fork s2 at t=0: GEMM depends only on x/W.
    cudaEventRecord(ev0, 0);
    cudaStreamWaitEvent(s2, ev0, 0);
    mz_gemm_mma<<<(NN + 127) / 128, 256, GEMM_SMEM, s2>>>(x, W);

    mz_init<<<(MP * NN + 255) / 256, 256>>>(ei32);
    mz_hist<<<dim3(512, MP), 256>>>(ei32, ew);
    mz_scanA<<<dim3(NT, MP), 256>>>();
    cudaEventRecord(evA, 0);

    // s2: after GEMM and scanA, scale h rows by dinv (overlaps fill).
    cudaStreamWaitEvent(s2, evA, 0);
    mz_hscale<<<2048, 256, 0, s2>>>();
    cudaEventRecord(ev1, s2);

    mz_fill<<<dim3(512, MP), 256>>>(ei32, ew);
    mz_scanB<<<MP, 64>>>();

    // Join: gather needs fill (main) + hscale (s2).
    cudaStreamWaitEvent(0, ev1, 0);
    mz_gather<<<dim3((NN + 7) / 8, MP), 256>>>(out);
}